// round 6
// baseline (speedup 1.0000x reference)
#include <cuda_runtime.h>
#include <cuda_bf16.h>
#include <cstdint>
#include <cstddef>

// ---------------------------------------------------------------------------
// ContentContrastiveLoss, GB300 (sm_103 target: mma.sync only, no tcgen05).
// Round 6: ONE persistent kernel. 148 normalize-CTAs stream the 128MB input
// (DRAM-bound) while 148 GEMM-CTAs consume screen tiles as row-groups become
// ready (tensor/L2-bound) -> GEMM hides under normalize.
//   loss = ( sum_offdiag max(0.2-||ci-aj||,0)^2 + sum_i ||ci-ai||^2 ) / (2N)
// CS screen: sim <= head_dot(512) + rc_i*ra_j ; flag if bound > 0.97.
// Diagonal exact fp32 during normalize. Last CTA: flags + finalize + reset.
// ---------------------------------------------------------------------------

#define NROWS 2048
#define DIM   8192
#define HEAD  512
#define TILE  128
#define KC    32          // bf16 K elems per GEMM chunk
#define SSTR  40          // smem row stride in bf16 elems (80B)
#define FCAP  4096
#define NNORM 148         // normalize CTAs
#define NGRID 296         // total CTAs (2 per SM, all co-resident)
#define NTILES ((NROWS / TILE) * (NROWS / TILE))   // 256
#define NGROUP (NROWS / TILE)                      // 16

__device__ __nv_bfloat16 g_Ch[(size_t)NROWS * HEAD];
__device__ __nv_bfloat16 g_Ah[(size_t)NROWS * HEAD];
__device__ float  g_rc[NROWS];
__device__ float  g_ra[NROWS];
__device__ float  g_invC[NROWS];
__device__ float  g_invA[NROWS];
__device__ int    g_groupdone[NGROUP];  // rows completed per 128-row group
__device__ int    g_tilectr;            // GEMM tile queue head
__device__ int    g_alldone;            // CTA completion counter
__device__ int    g_nflag;
__device__ int2   g_flags[FCAP];
__device__ double g_acc;

__device__ __forceinline__ uint32_t smem_u32(const void* p) {
    return (uint32_t)__cvta_generic_to_shared(p);
}
__device__ __forceinline__ void cp_async16(uint32_t dst, const void* src) {
    asm volatile("cp.async.cg.shared.global [%0], [%1], 16;" :: "r"(dst), "l"(src));
}
__device__ __forceinline__ void cp_commit() { asm volatile("cp.async.commit_group;"); }
template <int N>
__device__ __forceinline__ void cp_wait() {
    asm volatile("cp.async.wait_group %0;" :: "n"(N));
}
__device__ __forceinline__ void ldsm_x4(uint32_t (&r)[4], uint32_t addr) {
    asm volatile("ldmatrix.sync.aligned.m8n8.x4.shared.b16 {%0,%1,%2,%3}, [%4];"
                 : "=r"(r[0]), "=r"(r[1]), "=r"(r[2]), "=r"(r[3]) : "r"(addr));
}
__device__ __forceinline__ void mma_bf16(float (&d)[4], const uint32_t (&a)[4],
                                         const uint32_t b0, const uint32_t b1) {
    asm volatile(
        "mma.sync.aligned.m16n8k16.row.col.f32.bf16.bf16.f32 "
        "{%0,%1,%2,%3}, {%4,%5,%6,%7}, {%8,%9}, {%0,%1,%2,%3};"
        : "+f"(d[0]), "+f"(d[1]), "+f"(d[2]), "+f"(d[3])
        : "r"(a[0]), "r"(a[1]), "r"(a[2]), "r"(a[3]), "r"(b0), "r"(b1));
}
__device__ __forceinline__ float dot4(const float4 a, const float4 b) {
    return a.x * b.x + a.y * b.y + a.z * b.z + a.w * b.w;
}

// ---------------------------------------------------------------------------
// One fused persistent kernel.
// ---------------------------------------------------------------------------
__global__ void __launch_bounds__(256, 2) fused_kernel(
    const float* __restrict__ C, const float* __restrict__ A, float* out) {
    __shared__ __align__(16) __nv_bfloat16 sA[2][TILE * SSTR];
    __shared__ __align__(16) __nv_bfloat16 sB[2][TILE * SSTR];
    __shared__ float rcS[TILE], raS[TILE];
    __shared__ float redf[8][5];
    __shared__ int   sh_rank;

    const int bid  = blockIdx.x;
    const int tid  = threadIdx.x;
    const int wid  = tid >> 5;
    const int lane = tid & 31;

    // =================== ROLE 1: normalize (CTAs 0..147) ===================
    if (bid < NNORM) {
        for (int row = bid; row < NROWS; row += NNORM) {
            const float4* cs = (const float4*)(C + (size_t)row * DIM);
            const float4* as = (const float4*)(A + (size_t)row * DIM);

            float4 cv[8], av[8];
#pragma unroll
            for (int i = 0; i < 8; i++) cv[i] = cs[tid + i * 256];
#pragma unroll
            for (int i = 0; i < 8; i++) av[i] = as[tid + i * 256];

            float sC = 0.f, sA_ = 0.f, sD = 0.f;
#pragma unroll
            for (int i = 0; i < 8; i++) {
                sC  += dot4(cv[i], cv[i]);
                sA_ += dot4(av[i], av[i]);
                sD  += dot4(cv[i], av[i]);
            }
            const bool headT = tid < (HEAD / 4);
            const float hC = headT ? dot4(cv[0], cv[0]) : 0.f;
            const float hA = headT ? dot4(av[0], av[0]) : 0.f;

            float v5[5] = {sC, sA_, sD, hC, hA};
#pragma unroll
            for (int j = 0; j < 5; j++)
#pragma unroll
                for (int o = 16; o; o >>= 1)
                    v5[j] += __shfl_down_sync(0xFFFFFFFFu, v5[j], o);
            if (lane == 0)
#pragma unroll
                for (int j = 0; j < 5; j++) redf[wid][j] = v5[j];
            __syncthreads();
            float tC = 0.f, tA = 0.f, tD = 0.f, tHC = 0.f, tHA = 0.f;
#pragma unroll
            for (int w = 0; w < 8; w++) {
                tC += redf[w][0]; tA += redf[w][1]; tD += redf[w][2];
                tHC += redf[w][3]; tHA += redf[w][4];
            }
            const float invC = 1.0f / fmaxf(sqrtf(tC), 1e-12f);
            const float invA = 1.0f / fmaxf(sqrtf(tA), 1e-12f);

            if (headT) {
                __nv_bfloat162 lo = __floats2bfloat162_rn(cv[0].x * invC, cv[0].y * invC);
                __nv_bfloat162 hi = __floats2bfloat162_rn(cv[0].z * invC, cv[0].w * invC);
                uint2 p;
                p.x = *reinterpret_cast<uint32_t*>(&lo);
                p.y = *reinterpret_cast<uint32_t*>(&hi);
                ((uint2*)(g_Ch + (size_t)row * HEAD))[tid] = p;
                lo = __floats2bfloat162_rn(av[0].x * invA, av[0].y * invA);
                hi = __floats2bfloat162_rn(av[0].z * invA, av[0].w * invA);
                p.x = *reinterpret_cast<uint32_t*>(&lo);
                p.y = *reinterpret_cast<uint32_t*>(&hi);
                ((uint2*)(g_Ah + (size_t)row * HEAD))[tid] = p;
            }
            if (tid == 0) {
                const float sim = tD * invC * invA;
                atomicAdd(&g_acc, (double)fmaxf(2.0f - 2.0f * sim, 0.0f));
                g_invC[row] = invC;
                g_invA[row] = invA;
                g_rc[row] = sqrtf(fmaxf(1.0f - tHC * invC * invC, 0.0f));
                g_ra[row] = sqrtf(fmaxf(1.0f - tHA * invA * invA, 0.0f));
            }
            __syncthreads();           // all writes of this row issued
            if (tid == 0) {
                __threadfence();       // publish row data before counting it
                atomicAdd(&g_groupdone[row >> 7], 1);
            }
        }
    }

    // =================== ROLE 2: screen GEMM (all CTAs) ====================
    // Tiles ordered by band = max(ti,tj): q in [band^2, (band+1)^2).
    for (;;) {
        int q;
        if (tid == 0) sh_rank = atomicAdd(&g_tilectr, 1);
        __syncthreads();
        q = sh_rank;
        if (q >= NTILES) break;

        int band = (int)sqrtf((float)q);
        while ((band + 1) * (band + 1) <= q) band++;
        while (band * band > q) band--;
        const int pos = q - band * band;
        const int ti  = (pos <= band) ? band : (pos - band - 1);
        const int tj  = (pos <= band) ? pos  : band;

        // wait until both 128-row groups are normalized
        if (tid == 0) {
            while (atomicAdd(&g_groupdone[ti], 0) < TILE) __nanosleep(128);
            while (atomicAdd(&g_groupdone[tj], 0) < TILE) __nanosleep(128);
        }
        __syncthreads();
        __threadfence();  // acquire: make published head data visible

        const __nv_bfloat16* __restrict__ Ab = g_Ch + (size_t)ti * TILE * HEAD;
        const __nv_bfloat16* __restrict__ Bb = g_Ah + (size_t)tj * TILE * HEAD;

        const int warp_m = wid & 3;
        const int warp_n = wid >> 2;

        const __nv_bfloat16* t_src[4];
        uint32_t t_dst[4];
#pragma unroll
        for (int t = 0; t < 4; t++) {
            const int task  = tid + t * 256;
            const int which = task >> 9;
            const int r     = (task >> 2) & 127;
            const int seg   = task & 3;
            t_src[t] = (which ? Bb : Ab) + (size_t)r * HEAD + seg * 8;
            t_dst[t] = smem_u32((which ? &sB[0][0] : &sA[0][0]) + r * SSTR + seg * 8);
        }
        const uint32_t buf_bytes = TILE * SSTR * sizeof(__nv_bfloat16);

        uint32_t aAddr[2];
#pragma unroll
        for (int mf = 0; mf < 2; mf++) {
            const int r = warp_m * 32 + mf * 16 + (lane & 15);
            aAddr[mf] = smem_u32(&sA[0][0] + r * SSTR + (lane >> 4) * 8);
        }
        uint32_t bAddr[4];
#pragma unroll
        for (int p = 0; p < 4; p++) {
            const int r = warp_n * 64 + p * 16 + (lane & 7) + ((lane >> 4) & 1) * 8;
            bAddr[p] = smem_u32(&sB[0][0] + r * SSTR + ((lane >> 3) & 1) * 8);
        }

        float acc[2][8][4];
#pragma unroll
        for (int mf = 0; mf < 2; mf++)
#pragma unroll
            for (int nf = 0; nf < 8; nf++)
#pragma unroll
                for (int e = 0; e < 4; e++) acc[mf][nf][e] = 0.0f;

        if (tid < TILE) rcS[tid] = g_rc[ti * TILE + tid];
        else            raS[tid - TILE] = g_ra[tj * TILE + (tid - TILE)];

#pragma unroll
        for (int t = 0; t < 4; t++) cp_async16(t_dst[t], t_src[t]);
        cp_commit();

        const int NCHUNK = HEAD / KC;  // 16
        for (int k0 = 0; k0 < NCHUNK; k0++) {
            const uint32_t cur = (uint32_t)(k0 & 1) * buf_bytes;
            if (k0 + 1 < NCHUNK) {
                const uint32_t nxt = (uint32_t)((k0 + 1) & 1) * buf_bytes;
                const int koff = (k0 + 1) * KC;
#pragma unroll
                for (int t = 0; t < 4; t++) cp_async16(t_dst[t] + nxt, t_src[t] + koff);
                cp_commit();
                cp_wait<1>();
            } else {
                cp_wait<0>();
            }
            __syncthreads();

#pragma unroll
            for (int ks = 0; ks < 2; ks++) {
                uint32_t a[2][4];
#pragma unroll
                for (int mf = 0; mf < 2; mf++)
                    ldsm_x4(a[mf], aAddr[mf] + cur + ks * 32);
                uint32_t b[8][2];
#pragma unroll
                for (int p = 0; p < 4; p++) {
                    uint32_t r4[4];
                    ldsm_x4(r4, bAddr[p] + cur + ks * 32);
                    b[2 * p][0]     = r4[0];
                    b[2 * p][1]     = r4[1];
                    b[2 * p + 1][0] = r4[2];
                    b[2 * p + 1][1] = r4[3];
                }
#pragma unroll
                for (int mf = 0; mf < 2; mf++)
#pragma unroll
                    for (int nf = 0; nf < 8; nf++)
                        mma_bf16(acc[mf][nf], a[mf], b[nf][0], b[nf][1]);
            }
            __syncthreads();
        }

        // screen: flag if CS upper bound can reach sim > 0.98 (0.01 slack)
#pragma unroll
        for (int mf = 0; mf < 2; mf++) {
#pragma unroll
            for (int nf = 0; nf < 8; nf++) {
#pragma unroll
                for (int e = 0; e < 4; e++) {
                    const int li = warp_m * 32 + mf * 16 + (lane >> 2) + (e >> 1) * 8;
                    const int lj = warp_n * 64 + nf * 8 + (lane & 3) * 2 + (e & 1);
                    const int gi = ti * TILE + li;
                    const int gj = tj * TILE + lj;
                    if (gi == gj) continue;
                    const float bound = acc[mf][nf][e] + rcS[li] * raS[lj];
                    if (bound > 0.97f) {
                        const int idx = atomicAdd(&g_nflag, 1);
                        if (idx < FCAP) g_flags[idx] = make_int2(gi, gj);
                    }
                }
            }
        }
        __syncthreads();
    }

    // ============ TERMINAL: last CTA handles flags, finalizes, resets ======
    if (tid == 0) {
        __threadfence();
        sh_rank = atomicAdd(&g_alldone, 1);
    }
    __syncthreads();
    if (sh_rank == NGRID - 1) {
        __threadfence();  // see all other CTAs' flags/acc
        const int total = min(g_nflag, FCAP);
        for (int p = 0; p < total; p++) {   // expected: total == 0
            const int2 pr = g_flags[p];
            const float4* c = (const float4*)(C + (size_t)pr.x * DIM);
            const float4* a = (const float4*)(A + (size_t)pr.y * DIM);
            float s = 0.f;
            for (int i = tid; i < DIM / 4; i += 256) s += dot4(c[i], a[i]);
#pragma unroll
            for (int o = 16; o; o >>= 1) s += __shfl_down_sync(0xFFFFFFFFu, s, o);
            if (lane == 0) redf[wid][0] = s;
            __syncthreads();
            if (tid == 0) {
                float tot = 0.f;
#pragma unroll
                for (int w = 0; w < 8; w++) tot += redf[w][0];
                const float sim  = tot * g_invC[pr.x] * g_invA[pr.y];
                const float dist = sqrtf(fmaxf(2.0f - 2.0f * sim, 0.0f));
                const float diff = 0.2f - dist;
                if (diff > 0.0f) atomicAdd(&g_acc, (double)(diff * diff));
            }
            __syncthreads();
        }
        if (tid == 0) {
            const double tot = atomicAdd(&g_acc, 0.0);
            out[0] = (float)(tot / (2.0 * (double)NROWS));
            // reset all state for the next graph replay
            g_acc     = 0.0;
            g_nflag   = 0;
            g_tilectr = 0;
            g_alldone = 0;
#pragma unroll
            for (int g = 0; g < NGROUP; g++) g_groupdone[g] = 0;
        }
    }
}

extern "C" void kernel_launch(void* const* d_in, const int* in_sizes, int n_in,
                              void* d_out, int out_size) {
    (void)in_sizes; (void)n_in; (void)out_size;
    const float* C = (const float*)d_in[0];  // content_code
    const float* A = (const float*)d_in[1];  // audio_feature
    fused_kernel<<<NGRID, 256>>>(C, A, (float*)d_out);
}

// round 7
// speedup vs baseline: 1.3513x; 1.3513x over previous
#include <cuda_runtime.h>
#include <cuda_bf16.h>
#include <cstdint>
#include <cstddef>

// ---------------------------------------------------------------------------
// ContentContrastiveLoss, GB300 (sm_103 target: mma.sync only, no tcgen05).
// Round 7: serial normalize + screen-GEMM (fusion regressed in R6).
//   loss = ( sum_offdiag max(0.2-||ci-aj||,0)^2 + sum_i ||ci-ai||^2 ) / (2N)
// CS screen with HEAD=384: sim <= head_dot + rc_i*ra_j ; flag if > 0.97.
// Exact fp32 diagonal during normalize (stored per-row). GEMM's last CTA
// processes flags (expected none), sums diag, finalizes, resets state.
// ---------------------------------------------------------------------------

#define NROWS 2048
#define DIM   8192
#define HEAD  384
#define TILE  128
#define KC    32          // bf16 K elems per GEMM chunk
#define SSTR  40          // smem row stride in bf16 elems (80B)
#define FCAP  4096
#define NTILE ((NROWS / TILE) * (NROWS / TILE))   // 256

__device__ __nv_bfloat16 g_Ch[(size_t)NROWS * HEAD];
__device__ __nv_bfloat16 g_Ah[(size_t)NROWS * HEAD];
__device__ float  g_rc[NROWS];
__device__ float  g_ra[NROWS];
__device__ float  g_invC[NROWS];
__device__ float  g_invA[NROWS];
__device__ float  g_d2[NROWS];      // exact diagonal dist^2 per row
__device__ int    g_nflag;
__device__ int    g_done;
__device__ int2   g_flags[FCAP];
__device__ double g_acc;            // hinge accumulator (expected 0)

__device__ __forceinline__ uint32_t smem_u32(const void* p) {
    return (uint32_t)__cvta_generic_to_shared(p);
}
__device__ __forceinline__ void cp_async16(uint32_t dst, const void* src) {
    asm volatile("cp.async.cg.shared.global [%0], [%1], 16;" :: "r"(dst), "l"(src));
}
__device__ __forceinline__ void cp_commit() { asm volatile("cp.async.commit_group;"); }
template <int N>
__device__ __forceinline__ void cp_wait() {
    asm volatile("cp.async.wait_group %0;" :: "n"(N));
}
__device__ __forceinline__ void ldsm_x4(uint32_t (&r)[4], uint32_t addr) {
    asm volatile("ldmatrix.sync.aligned.m8n8.x4.shared.b16 {%0,%1,%2,%3}, [%4];"
                 : "=r"(r[0]), "=r"(r[1]), "=r"(r[2]), "=r"(r[3]) : "r"(addr));
}
__device__ __forceinline__ void mma_bf16(float (&d)[4], const uint32_t (&a)[4],
                                         const uint32_t b0, const uint32_t b1) {
    asm volatile(
        "mma.sync.aligned.m16n8k16.row.col.f32.bf16.bf16.f32 "
        "{%0,%1,%2,%3}, {%4,%5,%6,%7}, {%8,%9}, {%0,%1,%2,%3};"
        : "+f"(d[0]), "+f"(d[1]), "+f"(d[2]), "+f"(d[3])
        : "r"(a[0]), "r"(a[1]), "r"(a[2]), "r"(a[3]), "r"(b0), "r"(b1));
}
__device__ __forceinline__ float dot4(const float4 a, const float4 b) {
    return a.x * b.x + a.y * b.y + a.z * b.z + a.w * b.w;
}

// ---------------------------------------------------------------------------
// Kernel 1: per-row normalize. All 16 LDG.128 front-batched for max MLP.
// Outputs: bf16 heads (384), rc/ra tail fractions, invC/invA, exact diag d2.
// ---------------------------------------------------------------------------
__global__ void __launch_bounds__(256) normalize_kernel(
    const float* __restrict__ C, const float* __restrict__ A) {
    __shared__ float red[8][5];
    const int row = blockIdx.x;
    const int tid = threadIdx.x;

    const float4* cs = (const float4*)(C + (size_t)row * DIM);
    const float4* as = (const float4*)(A + (size_t)row * DIM);

    float4 cv[8], av[8];
#pragma unroll
    for (int i = 0; i < 8; i++) cv[i] = cs[tid + i * 256];
#pragma unroll
    for (int i = 0; i < 8; i++) av[i] = as[tid + i * 256];

    float sC = 0.f, sA = 0.f, sD = 0.f;
#pragma unroll
    for (int i = 0; i < 8; i++) {
        sC += dot4(cv[i], cv[i]);
        sA += dot4(av[i], av[i]);
        sD += dot4(cv[i], av[i]);
    }
    const bool headT = tid < (HEAD / 4);   // head = first 96 float4s
    const float hC = headT ? dot4(cv[0], cv[0]) : 0.f;
    const float hA = headT ? dot4(av[0], av[0]) : 0.f;

    float v5[5] = {sC, sA, sD, hC, hA};
#pragma unroll
    for (int j = 0; j < 5; j++)
#pragma unroll
        for (int o = 16; o; o >>= 1)
            v5[j] += __shfl_down_sync(0xFFFFFFFFu, v5[j], o);
    if ((tid & 31) == 0)
#pragma unroll
        for (int j = 0; j < 5; j++) red[tid >> 5][j] = v5[j];
    __syncthreads();
    float tC = 0.f, tA = 0.f, tD = 0.f, tHC = 0.f, tHA = 0.f;
#pragma unroll
    for (int w = 0; w < 8; w++) {
        tC += red[w][0]; tA += red[w][1]; tD += red[w][2];
        tHC += red[w][3]; tHA += red[w][4];
    }
    const float invC = 1.0f / fmaxf(sqrtf(tC), 1e-12f);
    const float invA = 1.0f / fmaxf(sqrtf(tA), 1e-12f);

    if (tid == 0) {
        const float sim = tD * invC * invA;
        g_d2[row]   = fmaxf(2.0f - 2.0f * sim, 0.0f);
        g_invC[row] = invC;
        g_invA[row] = invA;
        g_rc[row] = sqrtf(fmaxf(1.0f - tHC * invC * invC, 0.0f));
        g_ra[row] = sqrtf(fmaxf(1.0f - tHA * invA * invA, 0.0f));
    }

    if (headT) {
        __nv_bfloat162 lo = __floats2bfloat162_rn(cv[0].x * invC, cv[0].y * invC);
        __nv_bfloat162 hi = __floats2bfloat162_rn(cv[0].z * invC, cv[0].w * invC);
        uint2 p;
        p.x = *reinterpret_cast<uint32_t*>(&lo);
        p.y = *reinterpret_cast<uint32_t*>(&hi);
        ((uint2*)(g_Ch + (size_t)row * HEAD))[tid] = p;

        lo = __floats2bfloat162_rn(av[0].x * invA, av[0].y * invA);
        hi = __floats2bfloat162_rn(av[0].z * invA, av[0].w * invA);
        p.x = *reinterpret_cast<uint32_t*>(&lo);
        p.y = *reinterpret_cast<uint32_t*>(&hi);
        ((uint2*)(g_Ah + (size_t)row * HEAD))[tid] = p;
    }
}

// ---------------------------------------------------------------------------
// Kernel 2: 128x128-tile bf16 HMMA screen GEMM over K=HEAD=384, one tile
// per CTA. Last-done CTA: fallback flags (exact fp32), diag sum, finalize,
// state reset.
// ---------------------------------------------------------------------------
__global__ void __launch_bounds__(256) screen_gemm_kernel(
    const float* __restrict__ C, const float* __restrict__ A, float* out) {
    __shared__ __align__(16) __nv_bfloat16 sA[2][TILE * SSTR];
    __shared__ __align__(16) __nv_bfloat16 sB[2][TILE * SSTR];
    __shared__ float rcS[TILE], raS[TILE];
    __shared__ float redf[8];
    __shared__ int   sh_last;

    const int tid    = threadIdx.x;
    const int wid    = tid >> 5;
    const int lane   = tid & 31;
    const int warp_m = wid & 3;
    const int warp_n = wid >> 2;

    const int ti = blockIdx.y;
    const int tj = blockIdx.x;
    const __nv_bfloat16* __restrict__ Ab = g_Ch + (size_t)ti * TILE * HEAD;
    const __nv_bfloat16* __restrict__ Bb = g_Ah + (size_t)tj * TILE * HEAD;

    // global->shared tasks: 2 tiles x 128 rows x 4 segs(16B) = 1024, 4/thread
    const __nv_bfloat16* t_src[4];
    uint32_t t_dst[4];
#pragma unroll
    for (int t = 0; t < 4; t++) {
        const int task  = tid + t * 256;
        const int which = task >> 9;
        const int r     = (task >> 2) & 127;
        const int seg   = task & 3;
        t_src[t] = (which ? Bb : Ab) + (size_t)r * HEAD + seg * 8;
        t_dst[t] = smem_u32((which ? &sB[0][0] : &sA[0][0]) + r * SSTR + seg * 8);
    }
    const uint32_t buf_bytes = TILE * SSTR * sizeof(__nv_bfloat16);

    uint32_t aAddr[2];
#pragma unroll
    for (int mf = 0; mf < 2; mf++) {
        const int r = warp_m * 32 + mf * 16 + (lane & 15);
        aAddr[mf] = smem_u32(&sA[0][0] + r * SSTR + (lane >> 4) * 8);
    }
    uint32_t bAddr[4];
#pragma unroll
    for (int p = 0; p < 4; p++) {
        const int r = warp_n * 64 + p * 16 + (lane & 7) + ((lane >> 4) & 1) * 8;
        bAddr[p] = smem_u32(&sB[0][0] + r * SSTR + ((lane >> 3) & 1) * 8);
    }

    float acc[2][8][4];
#pragma unroll
    for (int mf = 0; mf < 2; mf++)
#pragma unroll
        for (int nf = 0; nf < 8; nf++)
#pragma unroll
            for (int e = 0; e < 4; e++) acc[mf][nf][e] = 0.0f;

    if (tid < TILE) rcS[tid] = g_rc[ti * TILE + tid];
    else            raS[tid - TILE] = g_ra[tj * TILE + (tid - TILE)];

#pragma unroll
    for (int t = 0; t < 4; t++) cp_async16(t_dst[t], t_src[t]);
    cp_commit();

    const int NCHUNK = HEAD / KC;  // 12
    for (int k0 = 0; k0 < NCHUNK; k0++) {
        const uint32_t cur = (uint32_t)(k0 & 1) * buf_bytes;
        if (k0 + 1 < NCHUNK) {
            const uint32_t nxt = (uint32_t)((k0 + 1) & 1) * buf_bytes;
            const int koff = (k0 + 1) * KC;
#pragma unroll
            for (int t = 0; t < 4; t++) cp_async16(t_dst[t] + nxt, t_src[t] + koff);
            cp_commit();
            cp_wait<1>();
        } else {
            cp_wait<0>();
        }
        __syncthreads();

#pragma unroll
        for (int ks = 0; ks < 2; ks++) {
            uint32_t a[2][4];
#pragma unroll
            for (int mf = 0; mf < 2; mf++)
                ldsm_x4(a[mf], aAddr[mf] + cur + ks * 32);
            uint32_t b[8][2];
#pragma unroll
            for (int p = 0; p < 4; p++) {
                uint32_t r4[4];
                ldsm_x4(r4, bAddr[p] + cur + ks * 32);
                b[2 * p][0]     = r4[0];
                b[2 * p][1]     = r4[1];
                b[2 * p + 1][0] = r4[2];
                b[2 * p + 1][1] = r4[3];
            }
#pragma unroll
            for (int mf = 0; mf < 2; mf++)
#pragma unroll
                for (int nf = 0; nf < 8; nf++)
                    mma_bf16(acc[mf][nf], a[mf], b[nf][0], b[nf][1]);
        }
        __syncthreads();
    }

    // ---- screen: flag if CS upper bound can reach sim > 0.98 (0.01 slack) ----
#pragma unroll
    for (int mf = 0; mf < 2; mf++) {
#pragma unroll
        for (int nf = 0; nf < 8; nf++) {
#pragma unroll
            for (int e = 0; e < 4; e++) {
                const int li = warp_m * 32 + mf * 16 + (lane >> 2) + (e >> 1) * 8;
                const int lj = warp_n * 64 + nf * 8 + (lane & 3) * 2 + (e & 1);
                const int gi = ti * TILE + li;
                const int gj = tj * TILE + lj;
                if (gi == gj) continue;  // diagonal handled exactly elsewhere
                const float bound = acc[mf][nf][e] + rcS[li] * raS[lj];
                if (bound > 0.97f) {
                    const int idx = atomicAdd(&g_nflag, 1);
                    if (idx < FCAP) g_flags[idx] = make_int2(gi, gj);
                }
            }
        }
    }

    // ---- terminal: last-done CTA -> fallback + diag sum + finalize + reset --
    if (tid == 0) {
        __threadfence();
        sh_last = atomicAdd(&g_done, 1);
    }
    __syncthreads();
    if (sh_last != NTILE - 1) return;
    __threadfence();  // acquire all other CTAs' flags / g_acc

    const int total = min(g_nflag, FCAP);
    for (int p = 0; p < total; p++) {   // expected: total == 0
        const int2 pr = g_flags[p];
        const float4* c = (const float4*)(C + (size_t)pr.x * DIM);
        const float4* a = (const float4*)(A + (size_t)pr.y * DIM);
        float s = 0.f;
        for (int i = tid; i < DIM / 4; i += 256) s += dot4(c[i], a[i]);
#pragma unroll
        for (int o = 16; o; o >>= 1) s += __shfl_down_sync(0xFFFFFFFFu, s, o);
        if (lane == 0) redf[wid] = s;
        __syncthreads();
        if (tid == 0) {
            float tot = 0.f;
#pragma unroll
            for (int w = 0; w < 8; w++) tot += redf[w];
            const float sim  = tot * g_invC[pr.x] * g_invA[pr.y];
            const float dist = sqrtf(fmaxf(2.0f - 2.0f * sim, 0.0f));
            const float diff = 0.2f - dist;
            if (diff > 0.0f) atomicAdd(&g_acc, (double)(diff * diff));
        }
        __syncthreads();
    }

    // exact diagonal sum (fp64 accumulation of 2048 fp32 values)
    double ds = 0.0;
#pragma unroll
    for (int i = 0; i < 8; i++) ds += (double)g_d2[tid + i * 256];
#pragma unroll
    for (int o = 16; o; o >>= 1) ds += __shfl_down_sync(0xFFFFFFFFu, ds, o);
    __syncthreads();
    __shared__ double redd[8];
    if (lane == 0) redd[wid] = ds;
    __syncthreads();
    if (tid == 0) {
        double tot = atomicAdd(&g_acc, 0.0);  // hinge part (usually 0)
#pragma unroll
        for (int w = 0; w < 8; w++) tot += redd[w];
        out[0] = (float)(tot / (2.0 * (double)NROWS));
        g_acc   = 0.0;   // reset for next graph replay
        g_nflag = 0;
        g_done  = 0;
    }
}

extern "C" void kernel_launch(void* const* d_in, const int* in_sizes, int n_in,
                              void* d_out, int out_size) {
    (void)in_sizes; (void)n_in; (void)out_size;
    const float* C = (const float*)d_in[0];  // content_code
    const float* A = (const float*)d_in[1];  // audio_feature

    normalize_kernel<<<NROWS, 256>>>(C, A);
    screen_gemm_kernel<<<dim3(NROWS / TILE, NROWS / TILE), 256>>>(C, A, (float*)d_out);
}